// round 15
// baseline (speedup 1.0000x reference)
#include <cuda_runtime.h>
#include <cuda_bf16.h>
#include <math.h>
#include <mma.h>

using namespace nvcuda;

#define B_    128
#define Q_    16
#define D_    1024
#define E_    300
#define K_    11
#define CTAS_PER_B 4
#define DOCS_PER_CTA 256
#define THREADS 256
#define NWARP 8
#define NCHUNK 10            // 10 chunks x 32 e = 320 (zero padded past 300)
#define QLD   324            // qn row stride (floats), covers e<320, mult of 4
#define CROW  36             // chunk row stride per doc (floats) = 9 float4
#define SSTRIDE 264

// shared layout (floats)
#define SM_QN    0
#define SM_TMP16 (Q_*QLD)            // 5184
#define SM_INVDD (SM_TMP16 + 16)     // 5200
#define SM_DTOK  (SM_INVDD + 256)    // 5456 (ints)
#define SM_BUF0  (SM_DTOK + 256)     // 5712 (16B aligned: 5712*4 % 16 == 0)
#define SM_BUF1  (SM_BUF0 + 256*CROW)// 5712 + 9216 = 14928
#define SM_TOTAL (SM_BUF1 + 256*CROW)// 24144 floats = 96576 B
// S (16 x 264 = 4224 floats) aliases BUF0 after the k-loop

__device__ float g_part[B_*CTAS_PER_B*Q_*13];
__device__ int   g_count[B_];

__global__ __launch_bounds__(THREADS, 2)
void knrm_tensor_kernel(const int* __restrict__ doctoks,
                        const int* __restrict__ querytoks,
                        const float* __restrict__ emb,
                        const float* __restrict__ mus,
                        const float* __restrict__ sigmas,
                        const float* __restrict__ fc_w,
                        const float* __restrict__ fc_b,
                        float* __restrict__ out)
{
    extern __shared__ float sm[];
    __shared__ int last_flag;
    float* qn     = sm + SM_QN;
    float* tmp16  = sm + SM_TMP16;
    float* inv_dd = sm + SM_INVDD;
    int*   dtok   = reinterpret_cast<int*>(sm + SM_DTOK);

    const int tid  = threadIdx.x;
    const int warp = tid >> 5;
    const int b    = blockIdx.x >> 2;
    const int cta  = blockIdx.x & 3;
    const int dbase = cta * DOCS_PER_CTA;

    // ---- doc tokens to shared ----
    dtok[tid] = doctoks[b*D_ + dbase + tid];

    // ---- load + normalize query embeddings (fp32), zero-pad e in [300,324) ----
    for (int i = tid; i < Q_*QLD; i += THREADS) {
        int q = i / QLD, e = i - q*QLD;
        int t = querytoks[b*Q_ + q];
        qn[i] = (e < E_) ? emb[(long)t*E_ + e] : 0.f;
    }
    __syncthreads();
    {
        int q = tid >> 4, l = tid & 15;    // 16 q x 16 lanes
        float ss = 0.f;
        for (int e = l; e < E_; e += 16) { float v = qn[q*QLD + e]; ss += v*v; }
        #pragma unroll
        for (int o = 8; o > 0; o >>= 1) ss += __shfl_down_sync(0xffffffffu, ss, o, 16);
        if (l == 0) tmp16[q] = 1.0f / (sqrtf(ss) + 1e-9f);
    }
    __syncthreads();
    for (int i = tid; i < Q_*QLD; i += THREADS) {
        int q = i / QLD;
        qn[i] *= tmp16[q];
    }

    const float4* embf4 = reinterpret_cast<const float4*>(emb);
    float4* buf4[2] = { reinterpret_cast<float4*>(sm + SM_BUF0),
                        reinterpret_cast<float4*>(sm + SM_BUF1) };

    auto stage = [&](int c, float4* buf) {
        #pragma unroll
        for (int k = 0; k < 8; k++) {
            int i = tid + (k << 8);            // 0..2047
            int doc = i >> 3, j = i & 7;       // 8 f4 per doc per chunk
            int g = c*8 + j;                   // global f4 index within row (75 real)
            float4 v = make_float4(0.f, 0.f, 0.f, 0.f);
            if (g < 75) v = embf4[(long)dtok[doc]*75 + g];
            buf[doc*9 + j] = v;
        }
    };

    // ---- accumulators: 2 wmma C tiles per warp (docs warp*32 .. +32) ----
    wmma::fragment<wmma::accumulator, 16, 16, 8, float> cf[2];
    wmma::fill_fragment(cf[0], 0.f);
    wmma::fill_fragment(cf[1], 0.f);
    float ddacc = 0.f;

    __syncthreads();
    stage(0, buf4[0]);
    __syncthreads();

    for (int c = 0; c < NCHUNK; c++) {
        if (c + 1 < NCHUNK) stage(c + 1, buf4[(c + 1) & 1]);

        float* bufc = reinterpret_cast<float*>(buf4[c & 1]);
        #pragma unroll
        for (int ks = 0; ks < 4; ks++) {
            wmma::fragment<wmma::matrix_a, 16, 16, 8, wmma::precision::tf32, wmma::row_major> af;
            wmma::load_matrix_sync(af, qn + c*32 + ks*8, QLD);
            #pragma unroll
            for (int i = 0; i < af.num_elements; i++) af.x[i] = wmma::__float_to_tf32(af.x[i]);
            #pragma unroll
            for (int t = 0; t < 2; t++) {
                wmma::fragment<wmma::matrix_b, 16, 16, 8, wmma::precision::tf32, wmma::col_major> bf;
                wmma::load_matrix_sync(bf, bufc + (warp*32 + t*16)*CROW + ks*8, CROW);
                #pragma unroll
                for (int i = 0; i < bf.num_elements; i++) bf.x[i] = wmma::__float_to_tf32(bf.x[i]);
                wmma::mma_sync(cf[t], af, bf, cf[t]);
            }
        }

        // doc-norm partial: thread t owns doc t (fp32, from the exact staged data)
        {
            const float4* myrow = buf4[c & 1] + tid*9;
            #pragma unroll
            for (int j = 0; j < 8; j++) {
                float4 v = myrow[j];
                ddacc = fmaf(v.x,v.x, fmaf(v.y,v.y, fmaf(v.z,v.z, fmaf(v.w,v.w, ddacc))));
            }
        }
        __syncthreads();
    }

    inv_dd[tid] = 1.0f / (sqrtf(ddacc) + 1e-9f);

    // ---- store raw dots to S (aliases BUF0; all buf reads are done) ----
    float* S = sm + SM_BUF0;   // 16 x 264
    wmma::store_matrix_sync(S + warp*32,      cf[0], SSTRIDE, wmma::mem_row_major);
    wmma::store_matrix_sync(S + warp*32 + 16, cf[1], SSTRIDE, wmma::mem_row_major);
    __syncthreads();

    // ---- RBF bank: 16 lanes per q; k=10 (sigma=1e-3) via exact token match ----
    const int myq = tid >> 4, myl = tid & 15;
    const int mytok = querytoks[b*Q_ + myq];
    float mu_r[K_], w_r[K_];
    #pragma unroll
    for (int k = 0; k < K_; k++) {
        mu_r[k] = mus[k];
        float sg = sigmas[k];
        w_r[k] = -0.5f/(sg*sg);
    }
    float kacc[K_];
    #pragma unroll
    for (int k = 0; k < K_; k++) kacc[k] = 0.f;
    float simacc = 0.f;

    #pragma unroll 4
    for (int j = myl; j < DOCS_PER_CTA; j += 16) {
        float s = S[myq*SSTRIDE + j] * inv_dd[j];
        simacc += s;
        #pragma unroll
        for (int k = 0; k < 10; k++) {
            float dif = s - mu_r[k];
            kacc[k] += __expf(w_r[k]*dif*dif);
        }
        int dt = dtok[j];
        if (dt == mytok && dt != 0) kacc[10] += 1.0f;
    }

    #pragma unroll
    for (int k = 0; k < K_; k++) {
        float v = kacc[k];
        #pragma unroll
        for (int o = 8; o > 0; o >>= 1) v += __shfl_down_sync(0xffffffffu, v, o, 16);
        kacc[k] = v;
    }
    {
        float v = simacc;
        #pragma unroll
        for (int o = 8; o > 0; o >>= 1) v += __shfl_down_sync(0xffffffffu, v, o, 16);
        simacc = v;
    }
    if (myl == 0) {
        float* dst = &g_part[(blockIdx.x*Q_ + myq)*13];
        #pragma unroll
        for (int k = 0; k < K_; k++) dst[k] = kacc[k];
        dst[11] = simacc;
    }

    // ---- fused finalization: last CTA of this batch reduces + scores ----
    __syncthreads();
    if (tid == 0) {
        __threadfence();
        int old = atomicAdd(&g_count[b], 1);
        last_flag = (old == CTAS_PER_B - 1);
    }
    __syncthreads();
    if (!last_flag) return;

    if (tid < 32) {
        __threadfence();
        const int lane = tid;
        const int q = lane & 15;
        const bool active = (lane < 16);

        float kb[K_];
        #pragma unroll
        for (int k = 0; k < K_; k++) kb[k] = 0.f;
        float sim = 0.f;
        #pragma unroll
        for (int cc = 0; cc < CTAS_PER_B; cc++) {
            const float* src = &g_part[((b*CTAS_PER_B + cc)*Q_ + q)*13];
            #pragma unroll
            for (int k = 0; k < K_; k++) kb[k] += src[k];
            sim += src[11];
        }
        const bool m = (sim != 0.0f) && active;
        float score = fc_b[0];
        #pragma unroll
        for (int k = 0; k < K_; k++) {
            float v = m ? logf(kb[k] + 1e-6f) : 0.0f;
            #pragma unroll
            for (int o = 8; o > 0; o >>= 1) v += __shfl_down_sync(0xffffffffu, v, o, 16);
            score = fmaf(v, fc_w[k], score);
        }
        if (lane == 0) {
            out[b] = score;
            g_count[b] = 0;
        }
    }
}

extern "C" void kernel_launch(void* const* d_in, const int* in_sizes, int n_in,
                              void* d_out, int out_size)
{
    const int*   doctoks   = (const int*)  d_in[0];
    const int*   querytoks = (const int*)  d_in[1];
    // d_in[2] = query_idf (unused)
    const float* emb       = (const float*)d_in[3];
    const float* mus       = (const float*)d_in[4];
    const float* sigmas    = (const float*)d_in[5];
    const float* fc_w      = (const float*)d_in[6];
    const float* fc_b      = (const float*)d_in[7];
    float* out = (float*)d_out;

    static bool attr_set = false;
    if (!attr_set) {
        cudaFuncSetAttribute(knrm_tensor_kernel,
                             cudaFuncAttributeMaxDynamicSharedMemorySize,
                             SM_TOTAL * (int)sizeof(float));
        attr_set = true;
    }
    knrm_tensor_kernel<<<B_*CTAS_PER_B, THREADS, SM_TOTAL * (int)sizeof(float)>>>(
        doctoks, querytoks, emb, mus, sigmas, fc_w, fc_b, out);
}

// round 16
// speedup vs baseline: 1.7094x; 1.7094x over previous
#include <cuda_runtime.h>
#include <cuda_bf16.h>
#include <math.h>
#include <mma.h>
#include <stdint.h>

using namespace nvcuda;

#define B_    128
#define Q_    16
#define D_    1024
#define E_    300
#define K_    11
#define CTAS_PER_B 4
#define DOCS_PER_CTA 256
#define THREADS 256
#define NCHUNK 10            // 10 chunks x 32 e = 320 (zero padded past 300)
#define QLD   324            // qn row stride (floats)
#define CROW  36             // chunk row stride per doc (floats) = 9 float4
#define SSTRIDE 264

// shared layout (floats)
#define SM_QN    0
#define SM_TMP16 (Q_*QLD)            // 5184
#define SM_INVDD (SM_TMP16 + 16)     // 5200
#define SM_DTOK  (SM_INVDD + 256)    // 5456 (ints)
#define SM_BUF0  (SM_DTOK + 256)     // 5712 (16B aligned)
#define SM_BUF1  (SM_BUF0 + 256*CROW)// 14928
#define SM_TOTAL (SM_BUF1 + 256*CROW)// 24144 floats = 96576 B
// S (16 x 264) aliases BUF0 after the k-loop

__device__ float g_part[B_*CTAS_PER_B*Q_*13];
__device__ int   g_count[B_];

__device__ __forceinline__ void cpa16(uint32_t dst, const void* src, int sz) {
    asm volatile("cp.async.cg.shared.global [%0], [%1], 16, %2;"
                 :: "r"(dst), "l"(src), "r"(sz));
}

__global__ __launch_bounds__(THREADS, 2)
void knrm_tensor_kernel(const int* __restrict__ doctoks,
                        const int* __restrict__ querytoks,
                        const float* __restrict__ emb,
                        const float* __restrict__ mus,
                        const float* __restrict__ sigmas,
                        const float* __restrict__ fc_w,
                        const float* __restrict__ fc_b,
                        float* __restrict__ out)
{
    extern __shared__ float sm[];
    __shared__ int last_flag;
    float* qn     = sm + SM_QN;
    float* tmp16  = sm + SM_TMP16;
    float* inv_dd = sm + SM_INVDD;
    int*   dtok   = reinterpret_cast<int*>(sm + SM_DTOK);

    const int tid  = threadIdx.x;
    const int warp = tid >> 5;
    const int b    = blockIdx.x >> 2;
    const int cta  = blockIdx.x & 3;
    const int dbase = cta * DOCS_PER_CTA;

    // ---- doc tokens to shared ----
    dtok[tid] = doctoks[b*D_ + dbase + tid];

    // ---- load + normalize query embeddings (fp32), zero-pad e in [300,324) ----
    for (int i = tid; i < Q_*QLD; i += THREADS) {
        int q = i / QLD, e = i - q*QLD;
        int t = querytoks[b*Q_ + q];
        qn[i] = (e < E_) ? emb[(long)t*E_ + e] : 0.f;
    }
    __syncthreads();
    {
        int q = tid >> 4, l = tid & 15;    // 16 q x 16 lanes
        float ss = 0.f;
        for (int e = l; e < E_; e += 16) { float v = qn[q*QLD + e]; ss += v*v; }
        #pragma unroll
        for (int o = 8; o > 0; o >>= 1) ss += __shfl_down_sync(0xffffffffu, ss, o, 16);
        if (l == 0) tmp16[q] = 1.0f / (sqrtf(ss) + 1e-9f);
    }
    __syncthreads();
    for (int i = tid; i < Q_*QLD; i += THREADS) {
        int q = i / QLD;
        qn[i] *= tmp16[q];
    }

    // ---- staging setup: thread owns slot j=tid&7 of docs (tid>>3)+32k ----
    const int jfix = tid & 7;
    const int doc0 = tid >> 3;
    const char* src_k[8];
    #pragma unroll
    for (int k = 0; k < 8; k++) {
        int tok = dtok[doc0 + k*32];
        src_k[k] = reinterpret_cast<const char*>(emb + (long)tok * E_) + jfix*16;
    }
    uint32_t stg0, stg1;
    {
        uint64_t a0, a1;
        asm("cvta.to.shared.u64 %0, %1;" : "=l"(a0) : "l"(sm + SM_BUF0));
        asm("cvta.to.shared.u64 %0, %1;" : "=l"(a1) : "l"(sm + SM_BUF1));
        uint32_t off = (uint32_t)((doc0*9 + jfix) * 16);
        stg0 = (uint32_t)a0 + off;
        stg1 = (uint32_t)a1 + off;
    }
    auto stage = [&](int c) {
        uint32_t base = (c & 1) ? stg1 : stg0;
        int sz = ((c*8 + jfix) < 75) ? 16 : 0;
        int goff = c * 128;                 // bytes along the row
        #pragma unroll
        for (int k = 0; k < 8; k++)
            cpa16(base + k*(288*16), src_k[k] + goff, sz);
        asm volatile("cp.async.commit_group;");
    };

    // ---- accumulators: 2 wmma C tiles per warp ----
    wmma::fragment<wmma::accumulator, 16, 16, 8, float> cf[2];
    wmma::fill_fragment(cf[0], 0.f);
    wmma::fill_fragment(cf[1], 0.f);
    float ddacc = 0.f;

    stage(0);
    stage(1);

    float* bufp[2] = { sm + SM_BUF0, sm + SM_BUF1 };

    for (int c = 0; c < NCHUNK; c++) {
        if (c < NCHUNK-1) { asm volatile("cp.async.wait_group 1;"); }
        else              { asm volatile("cp.async.wait_group 0;"); }
        __syncthreads();                    // chunk c visible to all warps

        float* bufc = bufp[c & 1];
        #pragma unroll
        for (int ks = 0; ks < 4; ks++) {
            wmma::fragment<wmma::matrix_a, 16, 16, 8, wmma::precision::tf32, wmma::row_major> af;
            wmma::load_matrix_sync(af, qn + c*32 + ks*8, QLD);
            #pragma unroll
            for (int i = 0; i < af.num_elements; i++) af.x[i] = wmma::__float_to_tf32(af.x[i]);
            #pragma unroll
            for (int t = 0; t < 2; t++) {
                wmma::fragment<wmma::matrix_b, 16, 16, 8, wmma::precision::tf32, wmma::col_major> bf;
                wmma::load_matrix_sync(bf, bufc + (warp*32 + t*16)*CROW + ks*8, CROW);
                #pragma unroll
                for (int i = 0; i < bf.num_elements; i++) bf.x[i] = wmma::__float_to_tf32(bf.x[i]);
                wmma::mma_sync(cf[t], af, bf, cf[t]);
            }
        }

        // doc-norm partial: thread t owns doc t
        {
            const float4* myrow = reinterpret_cast<const float4*>(bufc) + tid*9;
            #pragma unroll
            for (int j = 0; j < 8; j++) {
                float4 v = myrow[j];
                ddacc = fmaf(v.x,v.x, fmaf(v.y,v.y, fmaf(v.z,v.z, fmaf(v.w,v.w, ddacc))));
            }
        }
        __syncthreads();                    // all reads of buf[c&1] done
        if (c + 2 < NCHUNK) stage(c + 2);   // safe to overwrite buf[c&1]
    }

    inv_dd[tid] = 1.0f / (sqrtf(ddacc) + 1e-9f);
    __syncthreads();

    // ---- store raw dots to S (aliases BUF0; staging fully drained) ----
    float* S = sm + SM_BUF0;   // 16 x 264
    wmma::store_matrix_sync(S + warp*32,      cf[0], SSTRIDE, wmma::mem_row_major);
    wmma::store_matrix_sync(S + warp*32 + 16, cf[1], SSTRIDE, wmma::mem_row_major);
    __syncthreads();

    // ---- RBF bank: 16 lanes per q; k=10 (sigma=1e-3) via exact token match ----
    const int myq = tid >> 4, myl = tid & 15;
    const int mytok = querytoks[b*Q_ + myq];
    float mu_r[K_], w_r[K_];
    #pragma unroll
    for (int k = 0; k < K_; k++) {
        mu_r[k] = mus[k];
        float sg = sigmas[k];
        w_r[k] = -0.5f/(sg*sg);
    }
    float kacc[K_];
    #pragma unroll
    for (int k = 0; k < K_; k++) kacc[k] = 0.f;
    float simacc = 0.f;

    #pragma unroll 4
    for (int j = myl; j < DOCS_PER_CTA; j += 16) {
        float s = S[myq*SSTRIDE + j] * inv_dd[j];
        simacc += s;
        #pragma unroll
        for (int k = 0; k < 10; k++) {
            float dif = s - mu_r[k];
            kacc[k] += __expf(w_r[k]*dif*dif);
        }
        int dt = dtok[j];
        if (dt == mytok && dt != 0) kacc[10] += 1.0f;
    }

    #pragma unroll
    for (int k = 0; k < K_; k++) {
        float v = kacc[k];
        #pragma unroll
        for (int o = 8; o > 0; o >>= 1) v += __shfl_down_sync(0xffffffffu, v, o, 16);
        kacc[k] = v;
    }
    {
        float v = simacc;
        #pragma unroll
        for (int o = 8; o > 0; o >>= 1) v += __shfl_down_sync(0xffffffffu, v, o, 16);
        simacc = v;
    }
    if (myl == 0) {
        float* dst = &g_part[(blockIdx.x*Q_ + myq)*13];
        #pragma unroll
        for (int k = 0; k < K_; k++) dst[k] = kacc[k];
        dst[11] = simacc;
    }

    // ---- fused finalization ----
    __syncthreads();
    if (tid == 0) {
        __threadfence();
        int old = atomicAdd(&g_count[b], 1);
        last_flag = (old == CTAS_PER_B - 1);
    }
    __syncthreads();
    if (!last_flag) return;

    if (tid < 32) {
        __threadfence();
        const int lane = tid;
        const int q = lane & 15;
        const bool active = (lane < 16);

        float kb[K_];
        #pragma unroll
        for (int k = 0; k < K_; k++) kb[k] = 0.f;
        float sim = 0.f;
        #pragma unroll
        for (int cc = 0; cc < CTAS_PER_B; cc++) {
            const float* src = &g_part[((b*CTAS_PER_B + cc)*Q_ + q)*13];
            #pragma unroll
            for (int k = 0; k < K_; k++) kb[k] += src[k];
            sim += src[11];
        }
        const bool m = (sim != 0.0f) && active;
        float score = fc_b[0];
        #pragma unroll
        for (int k = 0; k < K_; k++) {
            float v = m ? logf(kb[k] + 1e-6f) : 0.0f;
            #pragma unroll
            for (int o = 8; o > 0; o >>= 1) v += __shfl_down_sync(0xffffffffu, v, o, 16);
            score = fmaf(v, fc_w[k], score);
        }
        if (lane == 0) {
            out[b] = score;
            g_count[b] = 0;
        }
    }
}

extern "C" void kernel_launch(void* const* d_in, const int* in_sizes, int n_in,
                              void* d_out, int out_size)
{
    const int*   doctoks   = (const int*)  d_in[0];
    const int*   querytoks = (const int*)  d_in[1];
    // d_in[2] = query_idf (unused)
    const float* emb       = (const float*)d_in[3];
    const float* mus       = (const float*)d_in[4];
    const float* sigmas    = (const float*)d_in[5];
    const float* fc_w      = (const float*)d_in[6];
    const float* fc_b      = (const float*)d_in[7];
    float* out = (float*)d_out;

    static bool attr_set = false;
    if (!attr_set) {
        cudaFuncSetAttribute(knrm_tensor_kernel,
                             cudaFuncAttributeMaxDynamicSharedMemorySize,
                             SM_TOTAL * (int)sizeof(float));
        attr_set = true;
    }
    knrm_tensor_kernel<<<B_*CTAS_PER_B, THREADS, SM_TOTAL * (int)sizeof(float)>>>(
        doctoks, querytoks, emb, mus, sigmas, fc_w, fc_b, out);
}